// round 1
// baseline (speedup 1.0000x reference)
#include <cuda_runtime.h>
#include <cuda_bf16.h>

// Problem: B=64, H=W=1024, patch=64 -> nh=nw=16, 256 patches/img, 16384 patches.
// final = mean_b( max_patch( mean_{64x64} |o - t| ) )

#define B 64
#define HW 1024
#define P 64
#define NPATCH_PER_IMG 256   // 16*16
#define NPATCH_TOTAL (B * NPATCH_PER_IMG)
#define PATCH_ELEMS (P * P)  // 4096

// Scratch: per-patch sum of |o-t|. Fully overwritten each launch (deterministic).
__device__ float g_patch_sums[NPATCH_TOTAL];

// One block per patch, 256 threads, each thread: 4 float4 pairs (16 elems).
__global__ __launch_bounds__(256) void patch_sum_kernel(
    const float* __restrict__ o, const float* __restrict__ t)
{
    const int patch = blockIdx.x;           // 0..16383
    const int img = patch >> 8;             // /256
    const int pid = patch & 255;
    const int ph = pid >> 4;                // patch row 0..15
    const int pw = pid & 15;                // patch col 0..15

    // element offset of patch origin
    const size_t base = (size_t)img * (HW * HW) + (size_t)ph * (P * HW) + (size_t)pw * P;
    const float4* __restrict__ o4 = reinterpret_cast<const float4*>(o + base);
    const float4* __restrict__ t4 = reinterpret_cast<const float4*>(t + base);

    const int tid = threadIdx.x;
    float acc = 0.0f;

    // 4096 elems = 1024 float4. Thread handles float4 indices tid + i*256.
    // float4 idx -> row = idx/16, col4 = idx%16; row stride = 1024 floats = 256 float4.
#pragma unroll
    for (int i = 0; i < 4; i++) {
        int idx = tid + i * 256;
        int row = idx >> 4;
        int col = idx & 15;
        int off = row * 256 + col;          // in float4 units
        float4 a = o4[off];
        float4 b = t4[off];
        acc += fabsf(a.x - b.x) + fabsf(a.y - b.y)
             + fabsf(a.z - b.z) + fabsf(a.w - b.w);
    }

    // warp reduce
#pragma unroll
    for (int s = 16; s > 0; s >>= 1)
        acc += __shfl_xor_sync(0xFFFFFFFFu, acc, s);

    __shared__ float warp_sums[8];
    const int lane = tid & 31;
    const int wid = tid >> 5;
    if (lane == 0) warp_sums[wid] = acc;
    __syncthreads();

    if (wid == 0) {
        float v = (lane < 8) ? warp_sums[lane] : 0.0f;
#pragma unroll
        for (int s = 4; s > 0; s >>= 1)
            v += __shfl_xor_sync(0xFFFFFFFFu, v, s);
        if (lane == 0) g_patch_sums[patch] = v;
    }
}

// One block per image: max over 256 patch sums, atomicAdd scaled mean into out.
__global__ __launch_bounds__(256) void image_max_kernel(float* __restrict__ out)
{
    const int img = blockIdx.x;
    const int tid = threadIdx.x;
    float v = g_patch_sums[img * NPATCH_PER_IMG + tid];

#pragma unroll
    for (int s = 16; s > 0; s >>= 1)
        v = fmaxf(v, __shfl_xor_sync(0xFFFFFFFFu, v, s));

    __shared__ float warp_max[8];
    const int lane = tid & 31;
    const int wid = tid >> 5;
    if (lane == 0) warp_max[wid] = v;
    __syncthreads();

    if (wid == 0) {
        float m = (lane < 8) ? warp_max[lane] : 0.0f;   // sums are >= 0
#pragma unroll
        for (int s = 4; s > 0; s >>= 1)
            m = fmaxf(m, __shfl_xor_sync(0xFFFFFFFFu, m, s));
        if (lane == 0)
            atomicAdd(out, m * (1.0f / (float)PATCH_ELEMS / (float)B));
    }
}

extern "C" void kernel_launch(void* const* d_in, const int* in_sizes, int n_in,
                              void* d_out, int out_size)
{
    const float* o = (const float*)d_in[0];
    const float* t = (const float*)d_in[1];
    // d_in[2] is patch_size=64, compile-time constant here.
    float* out = (float*)d_out;

    patch_sum_kernel<<<NPATCH_TOTAL, 256>>>(o, t);
    cudaMemsetAsync(out, 0, sizeof(float));
    image_max_kernel<<<B, 256>>>(out);
}

// round 3
// speedup vs baseline: 1.0116x; 1.0116x over previous
#include <cuda_runtime.h>
#include <cuda_bf16.h>

// B=64, H=W=1024, patch=64 -> 16 x 16 = 256 patches/img, 16384 patches total.
// final = mean_b( max_patch( mean_{64x64} |o - t| ) )
// Single fused kernel: per-patch sum -> per-image atomicMax (uint bits) ->
// last-block reduces 64 maxes, writes scalar, re-zeroes maxes for next replay.

#define B 64
#define HW 1024
#define P 64
#define NPATCH_PER_IMG 256
#define NPATCH_TOTAL (B * NPATCH_PER_IMG)   // 16384
#define PATCH_ELEMS (P * P)                 // 4096

// Zero-initialized device globals. g_img_max is re-zeroed by the last block of
// every launch, so each replay starts from a clean state. g_counter is
// monotone (wrap-safe); last-block detection uses modulo.
__device__ unsigned int g_img_max[B];
__device__ unsigned int g_counter;

__global__ __launch_bounds__(256) void patch_loss_fused_kernel(
    const float* __restrict__ o, const float* __restrict__ t,
    float* __restrict__ out)
{
    const int patch = blockIdx.x;           // 0..16383
    const int img = patch >> 8;
    const int pid = patch & 255;
    const int ph = pid >> 4;
    const int pw = pid & 15;

    const size_t base = (size_t)img * (HW * HW) + (size_t)ph * (P * HW) + (size_t)pw * P;
    const float4* __restrict__ o4 = reinterpret_cast<const float4*>(o + base);
    const float4* __restrict__ t4 = reinterpret_cast<const float4*>(t + base);

    const int tid = threadIdx.x;
    float acc = 0.0f;

    // 4096 elems = 1024 float4; thread handles float4 idx tid + i*256.
    // idx -> row = idx/16, col = idx%16; row stride = 256 float4.
#pragma unroll
    for (int i = 0; i < 4; i++) {
        int idx = tid + i * 256;
        int off = ((idx >> 4) << 8) + (idx & 15);   // row*256 + col
        float4 a = __ldcs(&o4[off]);
        float4 b = __ldcs(&t4[off]);
        acc += fabsf(a.x - b.x) + fabsf(a.y - b.y)
             + fabsf(a.z - b.z) + fabsf(a.w - b.w);
    }

    // warp reduce
#pragma unroll
    for (int s = 16; s > 0; s >>= 1)
        acc += __shfl_xor_sync(0xFFFFFFFFu, acc, s);

    __shared__ float warp_sums[8];
    __shared__ bool s_is_last;
    const int lane = tid & 31;
    const int wid = tid >> 5;
    if (lane == 0) warp_sums[wid] = acc;
    __syncthreads();

    if (tid == 0) {
        float v = warp_sums[0] + warp_sums[1] + warp_sums[2] + warp_sums[3]
                + warp_sums[4] + warp_sums[5] + warp_sums[6] + warp_sums[7];
        // sums are >= 0 -> float bits are monotone as unsigned
        atomicMax(&g_img_max[img], __float_as_uint(v));
        __threadfence();
        unsigned int old = atomicAdd(&g_counter, 1u);
        s_is_last = ((old % NPATCH_TOTAL) == (NPATCH_TOTAL - 1));
    }
    __syncthreads();

    if (s_is_last) {
        // All 16384 blocks' atomicMax ops are globally visible (fence+counter).
        __threadfence();
        if (wid < 2) {
            int i = wid * 32 + lane;        // 0..63
            unsigned int bits = atomicOr(&g_img_max[i], 0u);  // atomic read
            float m = __uint_as_float(bits);
#pragma unroll
            for (int s = 16; s > 0; s >>= 1)
                m += __shfl_xor_sync(0xFFFFFFFFu, m, s);
            if (lane == 0) warp_sums[wid] = m;
        }
        __syncthreads();
        if (tid == 0)
            *out = (warp_sums[0] + warp_sums[1])
                 * (1.0f / (float)PATCH_ELEMS / (float)B);
        __syncthreads();
        // reset for next replay
        if (tid < B) g_img_max[tid] = 0u;
    }
}

extern "C" void kernel_launch(void* const* d_in, const int* in_sizes, int n_in,
                              void* d_out, int out_size)
{
    const float* o = (const float*)d_in[0];
    const float* t = (const float*)d_in[1];
    float* out = (float*)d_out;
    patch_loss_fused_kernel<<<NPATCH_TOTAL, 256>>>(o, t, out);
}